// round 7
// baseline (speedup 1.0000x reference)
#include <cuda_runtime.h>
#include <math.h>

#define NROWS 8192      // B*T = 32*256
#define DIMC  6625
#define DIMD  96
#define BLK   256
#define NWARP (BLK / 32)

__device__ float g_rowdist[NROWS];
__device__ int   g_done = 0;     // block-completion counter (self-resetting)

// Combine (val,idx) keeping larger val; on tie keep SMALLER index
// (jnp.argmax first-occurrence semantics).
__device__ __forceinline__ void amax_combine(float& mv, int& mi, float ov, int oi)
{
    if (ov > mv || (ov == mv && oi < mi)) { mv = ov; mi = oi; }
}

__device__ __forceinline__ void amax4(float4 v, int e, float& bv, int& bi)
{
    if (v.x > bv) { bv = v.x; bi = e;     }
    if (v.y > bv) { bv = v.y; bi = e + 1; }
    if (v.z > bv) { bv = v.z; bi = e + 2; }
    if (v.w > bv) { bv = v.w; bi = e + 3; }
}

// One block per row: argmax over predicts[n, :] (vectorized), then clipped
// squared distance from features[n] to centers[label]. Last finishing block
// performs the deterministic fixed-tree mean over all rows.
__global__ void __launch_bounds__(BLK) center_loss_kernel(
    const float* __restrict__ features,   // [NROWS, 96]
    const float* __restrict__ predicts,   // [NROWS, 6625]
    const float* __restrict__ centers,    // [6625, 96]
    float* __restrict__ out)
{
    const int n    = blockIdx.x;
    const int tid  = threadIdx.x;
    const int lane = tid & 31;
    const int wid  = tid >> 5;

    __shared__ float swval[NWARP];
    __shared__ int   swidx[NWARP];
    __shared__ int   s_label;
    __shared__ float s_part[3 * NWARP];
    __shared__ int   s_is_last;
    __shared__ float sred[BLK];

    const float* p = predicts + (size_t)n * DIMC;

    float bv = -INFINITY;
    int   bi = 0;

    // ---- alignment prologue: row element base n*6625 ≡ n (mod 4) ----
    const int s = (4 - (n & 3)) & 3;      // scalar elements before 16B boundary
    if (tid < s) {
        float v = p[tid];
        if (v > bv) { bv = v; bi = tid; }
    }

    // ---- vectorized main scan: float4 loads (LDG.128) ----
    const float4* p4 = (const float4*)(p + s);
    const int n4  = (DIMC - s) >> 2;      // ~1656 float4s
    int i = tid;
    // unroll-by-4 groups: 4 independent LDG.128 in flight per thread
    for (; i + 3 * BLK < n4; i += 4 * BLK) {
        float4 v0 = p4[i];
        float4 v1 = p4[i + 1 * BLK];
        float4 v2 = p4[i + 2 * BLK];
        float4 v3 = p4[i + 3 * BLK];
        amax4(v0, s + 4 * i,               bv, bi);
        amax4(v1, s + 4 * (i + 1 * BLK),   bv, bi);
        amax4(v2, s + 4 * (i + 2 * BLK),   bv, bi);
        amax4(v3, s + 4 * (i + 3 * BLK),   bv, bi);
    }
    for (; i < n4; i += BLK) {
        float4 v = p4[i];
        amax4(v, s + 4 * i, bv, bi);
    }

    // ---- scalar tail ----
    const int rem  = (DIMC - s) & 3;
    const int tail = DIMC - rem;
    if (tid < rem) {
        float v = p[tail + tid];
        if (v > bv) { bv = v; bi = tail + tid; }
    }

    // ---- warp argmax combine ----
    #pragma unroll
    for (int sh = 16; sh > 0; sh >>= 1) {
        float ov = __shfl_down_sync(0xFFFFFFFFu, bv, sh);
        int   oi = __shfl_down_sync(0xFFFFFFFFu, bi, sh);
        amax_combine(bv, bi, ov, oi);
    }
    if (lane == 0) { swval[wid] = bv; swidx[wid] = bi; }
    __syncthreads();

    if (tid == 0) {
        float mv = swval[0];
        int   mi = swidx[0];
        #pragma unroll
        for (int w = 1; w < NWARP; w++)
            amax_combine(mv, mi, swval[w], swidx[w]);
        s_label = mi;
    }
    __syncthreads();
    const int label = s_label;

    // ---- dot products over D=96 on first 3 warps ----
    float pf = 0.f, pc = 0.f, pd = 0.f;
    if (tid < DIMD) {
        float f  = features[(size_t)n * DIMD + tid];
        float cc = centers[(size_t)label * DIMD + tid];
        pf = f * f;
        pc = cc * cc;
        pd = f * cc;
    }
    if (wid < 3) {
        #pragma unroll
        for (int sh = 16; sh > 0; sh >>= 1) {
            pf += __shfl_down_sync(0xFFFFFFFFu, pf, sh);
            pc += __shfl_down_sync(0xFFFFFFFFu, pc, sh);
            pd += __shfl_down_sync(0xFFFFFFFFu, pd, sh);
        }
        if (lane == 0) {
            s_part[wid]             = pf;
            s_part[NWARP + wid]     = pc;
            s_part[2 * NWARP + wid] = pd;
        }
    }
    __syncthreads();

    if (tid == 0) {
        float sum_ff = s_part[0] + s_part[1] + s_part[2];
        float sum_cc = s_part[NWARP] + s_part[NWARP + 1] + s_part[NWARP + 2];
        float sum_fc = s_part[2 * NWARP] + s_part[2 * NWARP + 1] + s_part[2 * NWARP + 2];
        float dist = sum_ff + sum_cc - 2.0f * sum_fc;
        const float EPS  = 1e-07f;
        const float INFC = 100000000000.0f;
        dist = fminf(fmaxf(dist, EPS), INFC);
        g_rowdist[n] = dist;

        // publish, then count this block as done
        __threadfence();
        int prev = atomicAdd(&g_done, 1);
        s_is_last = (prev == NROWS - 1) ? 1 : 0;
    }
    __syncthreads();

    // ---- last block: deterministic fixed-tree mean over all rows ----
    if (s_is_last) {
        float acc = 0.f;
        #pragma unroll 8
        for (int r = tid; r < NROWS; r += BLK)
            acc += g_rowdist[r];
        sred[tid] = acc;
        __syncthreads();
        #pragma unroll
        for (int sh = BLK / 2; sh > 0; sh >>= 1) {
            if (tid < sh) sred[tid] += sred[tid + sh];
            __syncthreads();
        }
        if (tid == 0) {
            out[0] = sred[0] / (float)NROWS;
            g_done = 0;   // reset for next graph replay
        }
    }
}

extern "C" void kernel_launch(void* const* d_in, const int* in_sizes, int n_in,
                              void* d_out, int out_size)
{
    const float* features = (const float*)d_in[0];  // [32,256,96]
    const float* predicts = (const float*)d_in[1];  // [32,256,6625]
    const float* centers  = (const float*)d_in[2];  // [6625,96]
    float* out = (float*)d_out;

    center_loss_kernel<<<NROWS, BLK>>>(features, predicts, centers, out);
}